// round 3
// baseline (speedup 1.0000x reference)
#include <cuda_runtime.h>

// Haar DWT2, single level.
// x: [8, 64, 512, 512] f32  ->  out: 4 subbands (ll, lh, hl, hh) concatenated,
// each [8, 64, 256, 256] f32.
//
// Pure streaming kernel: each thread consumes a 2x8 input patch (4 float4 loads)
// and produces a float4 for each of the 4 subbands (4 float4 stores).
// All transactions are 128-bit and fully coalesced.

#define BC_TOTAL   512        // 8 * 64
#define H_IN       512
#define W_IN       512
#define H_OUT      256
#define W_OUT      256
#define QUADS_W    64         // W_OUT / 4
#define SUBBAND_N  33554432u  // BC_TOTAL * H_OUT * W_OUT

__global__ void __launch_bounds__(256, 8)
haar_dwt2_kernel(const float* __restrict__ x, float* __restrict__ out)
{
    unsigned tid = blockIdx.x * blockDim.x + threadIdx.x;

    // Decompose: tid = ((bc * 256) + i) * 64 + q   (all powers of two -> shifts)
    unsigned q  = tid & 63u;          // quad index along output width (j0 = 4*q)
    unsigned i  = (tid >> 6) & 255u;  // output row
    unsigned bc = tid >> 14;          // fused batch*channel index (0..511)

    // Input base: element ((bc*512 + 2*i) * 512 + 8*q)
    unsigned in_base = ((bc << 9) + (i << 1)) * (unsigned)W_IN + (q << 3);

    const float4* p0 = (const float4*)(x + in_base);            // row 2i
    const float4* p1 = (const float4*)(x + in_base + W_IN);     // row 2i+1

    // Front-batched independent loads (MLP = 4)
    float4 r0a = p0[0];
    float4 r0b = p0[1];
    float4 r1a = p1[0];
    float4 r1b = p1[1];

    // De-interleave columns: a = even cols (row 2i), b = odd cols (row 2i),
    //                        c = even cols (row 2i+1), d = odd cols (row 2i+1)
    float4 a = make_float4(r0a.x, r0a.z, r0b.x, r0b.z);
    float4 b = make_float4(r0a.y, r0a.w, r0b.y, r0b.w);
    float4 c = make_float4(r1a.x, r1a.z, r1b.x, r1b.z);
    float4 d = make_float4(r1a.y, r1a.w, r1b.y, r1b.w);

    const float s = 0.5f;

    float4 ll, lh, hl, hh;
    ll.x = (a.x + b.x + c.x + d.x) * s;
    ll.y = (a.y + b.y + c.y + d.y) * s;
    ll.z = (a.z + b.z + c.z + d.z) * s;
    ll.w = (a.w + b.w + c.w + d.w) * s;

    lh.x = (a.x + b.x - c.x - d.x) * s;
    lh.y = (a.y + b.y - c.y - d.y) * s;
    lh.z = (a.z + b.z - c.z - d.z) * s;
    lh.w = (a.w + b.w - c.w - d.w) * s;

    hl.x = (a.x - b.x + c.x - d.x) * s;
    hl.y = (a.y - b.y + c.y - d.y) * s;
    hl.z = (a.z - b.z + c.z - d.z) * s;
    hl.w = (a.w - b.w + c.w - d.w) * s;

    hh.x = (a.x - b.x - c.x + d.x) * s;
    hh.y = (a.y - b.y - c.y + d.y) * s;
    hh.z = (a.z - b.z - c.z + d.z) * s;
    hh.w = (a.w - b.w - c.w + d.w) * s;

    // Output element offset within a subband: ((bc*256 + i) * 256 + 4*q)
    unsigned out_off = (((bc << 8) + i) << 8) + (q << 2);

    float4* o0 = (float4*)(out + out_off);                       // ll
    float4* o1 = (float4*)(out + SUBBAND_N     + out_off);       // lh
    float4* o2 = (float4*)(out + 2u*SUBBAND_N  + out_off);       // hl
    float4* o3 = (float4*)(out + 3u*SUBBAND_N  + out_off);       // hh

    *o0 = ll;
    *o1 = lh;
    *o2 = hl;
    *o3 = hh;
}

extern "C" void kernel_launch(void* const* d_in, const int* in_sizes, int n_in,
                              void* d_out, int out_size)
{
    const float* x = (const float*)d_in[0];
    float* out = (float*)d_out;

    // Total quads = 512 * 256 * 64 = 8,388,608 threads; 256 threads/block
    dim3 grid(8388608u / 256u);
    dim3 block(256);
    haar_dwt2_kernel<<<grid, block>>>(x, out);
}